// round 2
// baseline (speedup 1.0000x reference)
#include <cuda_runtime.h>

#define TT   128
#define BLK  128

// ---- shared layout (floats) ----
// per-LSTM block: WihT[5][20] (100) + WhhT[5][20] (100) + Bsum[20] = 220
#define L1_OFF 0
#define L2_OFF 220
#define L3_OFF 440
#define FC_OFF 660
#define FW1 (FC_OFF)
#define FB1 (FW1+640)
#define FW2 (FB1+32)
#define FB2 (FW2+1024)
#define FW3 (FB2+32)
#define FB3 (FW3+512)
#define FW4 (FB3+16)
#define FB4 (FW4+256)
#define FW5 (FB4+16)
#define FB5 (FW5+80)
#define S_TOTAL (FB5+5)   // 3273 floats = ~13.1 KB

// HW tanh (1 MUFU on sm_75+). sigmoid(x) = 0.5*tanh(x/2)+0.5.
__device__ __forceinline__ float tanh_fast(float x) {
    float y;
    asm("tanh.approx.f32 %0, %1;" : "=f"(y) : "f"(x));
    return y;
}
__device__ __forceinline__ float sigm_fast(float x) {
    return fmaf(tanh_fast(0.5f * x), 0.5f, 0.5f);
}

// Packed dual-FMA: d = a*b + c per 32-bit half. Only reachable via PTX fma.rn.f32x2.
__device__ __forceinline__ float2 ffma2(float2 a, float2 b, float2 c) {
    float2 d;
    asm("{\n\t"
        ".reg .b64 ra, rb, rc, rd;\n\t"
        "mov.b64 ra, {%2, %3};\n\t"
        "mov.b64 rb, {%4, %5};\n\t"
        "mov.b64 rc, {%6, %7};\n\t"
        "fma.rn.f32x2 rd, ra, rb, rc;\n\t"
        "mov.b64 {%0, %1}, rd;\n\t"
        "}"
        : "=f"(d.x), "=f"(d.y)
        : "f"(a.x), "f"(a.y), "f"(b.x), "f"(b.y), "f"(c.x), "f"(c.y));
    return d;
}

// One LSTM cell step, packed math. sW: WihT[5][20] then WhhT[5][20] at +100; sB: fused bias[20].
__device__ __forceinline__ void lstm_step(const float* __restrict__ sW,
                                          const float* __restrict__ sB,
                                          const float* __restrict__ x,
                                          float* __restrict__ h,
                                          float* __restrict__ c) {
    float2 g[10];
    {
        const float4* b4 = reinterpret_cast<const float4*>(sB);
        #pragma unroll
        for (int q = 0; q < 5; q++) {
            float4 v = b4[q];
            g[2*q]   = make_float2(v.x, v.y);
            g[2*q+1] = make_float2(v.z, v.w);
        }
    }
    #pragma unroll
    for (int k = 0; k < 5; k++) {
        float2 xk = make_float2(x[k], x[k]);
        const float4* w4 = reinterpret_cast<const float4*>(sW + k * 20);
        #pragma unroll
        for (int q = 0; q < 5; q++) {
            float4 w = w4[q];
            g[2*q]   = ffma2(make_float2(w.x, w.y), xk, g[2*q]);
            g[2*q+1] = ffma2(make_float2(w.z, w.w), xk, g[2*q+1]);
        }
    }
    #pragma unroll
    for (int k = 0; k < 5; k++) {
        float2 hk = make_float2(h[k], h[k]);
        const float4* u4 = reinterpret_cast<const float4*>(sW + 100 + k * 20);
        #pragma unroll
        for (int q = 0; q < 5; q++) {
            float4 u = u4[q];
            g[2*q]   = ffma2(make_float2(u.x, u.y), hk, g[2*q]);
            g[2*q+1] = ffma2(make_float2(u.z, u.w), hk, g[2*q+1]);
        }
    }
    float ga[20];
    #pragma unroll
    for (int q = 0; q < 10; q++) { ga[2*q] = g[q].x; ga[2*q+1] = g[q].y; }

    #pragma unroll
    for (int m = 0; m < 5; m++) {
        float ig = sigm_fast(ga[m]);
        float fg = sigm_fast(ga[5 + m]);
        float gg = tanh_fast(ga[10 + m]);
        float og = sigm_fast(ga[15 + m]);
        float cm = fmaf(fg, c[m], ig * gg);
        c[m] = cm;
        h[m] = og * tanh_fast(cm);
    }
}

// Load one 4-timestep chunk (20 floats, 16B-aligned) into registers.
__device__ __forceinline__ void load_chunk(float* dst, const float* src) {
    const float4* s4 = reinterpret_cast<const float4*>(src);
    #pragma unroll
    for (int i = 0; i < 5; i++) {
        float4 v = __ldg(s4 + i);
        dst[4*i + 0] = v.x; dst[4*i + 1] = v.y;
        dst[4*i + 2] = v.z; dst[4*i + 3] = v.w;
    }
}

struct Params {
    const float *x1, *x2;
    const float *Wih1, *Whh1, *bih1, *bhh1;
    const float *Wih2a, *Whh2a, *bih2a, *bhh2a;
    const float *Wih2b, *Whh2b, *bih2b, *bhh2b;
    const float *W1, *b1, *W2, *b2, *W3, *b3, *W4, *b4, *W5, *b5;
    float* out;
    int B;
};

__global__ __launch_bounds__(BLK, 1)
void dynrnn_kernel(Params p) {
    __shared__ float s[S_TOTAL];
    const int tid = threadIdx.x;

    // ---- cooperative weight staging (transposed LSTM weights) ----
    {
        const float* srcs[6] = { p.Wih1, p.Whh1, p.Wih2a, p.Whh2a, p.Wih2b, p.Whh2b };
        const int    offs[6] = { L1_OFF, L1_OFF+100, L2_OFF, L2_OFF+100, L3_OFF, L3_OFF+100 };
        for (int m = 0; m < 6; m++) {
            const float* W = srcs[m];
            int off = offs[m];
            for (int i = tid; i < 100; i += BLK) {
                int j = i / 5, k = i % 5;
                s[off + k * 20 + j] = W[i];
            }
        }
        for (int i = tid; i < 20; i += BLK) {
            s[L1_OFF + 200 + i] = p.bih1[i]  + p.bhh1[i];
            s[L2_OFF + 200 + i] = p.bih2a[i] + p.bhh2a[i];
            s[L3_OFF + 200 + i] = p.bih2b[i] + p.bhh2b[i];
        }
        for (int i = tid; i < 640;  i += BLK) s[FW1 + i] = p.W1[i];
        for (int i = tid; i < 32;   i += BLK) s[FB1 + i] = p.b1[i];
        for (int i = tid; i < 1024; i += BLK) s[FW2 + i] = p.W2[i];
        for (int i = tid; i < 32;   i += BLK) s[FB2 + i] = p.b2[i];
        for (int i = tid; i < 512;  i += BLK) s[FW3 + i] = p.W3[i];
        for (int i = tid; i < 16;   i += BLK) s[FB3 + i] = p.b3[i];
        for (int i = tid; i < 256;  i += BLK) s[FW4 + i] = p.W4[i];
        for (int i = tid; i < 16;   i += BLK) s[FB4 + i] = p.b4[i];
        for (int i = tid; i < 80;   i += BLK) s[FW5 + i] = p.W5[i];
        for (int i = tid; i < 5;    i += BLK) s[FB5 + i] = p.b5[i];
    }
    __syncthreads();

    const int b = blockIdx.x * BLK + tid;
    if (b >= p.B) return;

    const float* __restrict__ x1p = p.x1 + (size_t)b * TT * 5;
    const float* __restrict__ x2p = p.x2 + (size_t)b * TT * 5;

    float h1[5], c1[5], h2a[5], c2a[5], h2b[5], c2b[5];
    #pragma unroll
    for (int m = 0; m < 5; m++) {
        h1[m] = c1[m] = h2a[m] = c2a[m] = h2b[m] = c2b[m] = 0.0f;
    }

    // double-buffered 4-timestep register chunks, prefetched one chunk ahead
    float A0[20], B0[20], A1[20], B1[20];
    load_chunk(A0, x1p);
    load_chunk(B0, x2p);

    #pragma unroll 1
    for (int it = 0; it < 16; it++) {
        // prefetch odd chunk
        {
            int ci = 2 * it + 1;
            load_chunk(A1, x1p + ci * 20);
            load_chunk(B1, x2p + ci * 20);
        }
        #pragma unroll
        for (int tl = 0; tl < 4; tl++) {
            lstm_step(&s[L1_OFF], &s[L1_OFF + 200], &A0[tl * 5], h1,  c1);
            lstm_step(&s[L2_OFF], &s[L2_OFF + 200], &B0[tl * 5], h2a, c2a);
            lstm_step(&s[L3_OFF], &s[L3_OFF + 200], h2a,         h2b, c2b);
        }
        // prefetch even chunk (clamped on last iter; redundant load is harmless)
        {
            int ci = (2 * it + 2 < 32) ? (2 * it + 2) : 31;
            load_chunk(A0, x1p + ci * 20);
            load_chunk(B0, x2p + ci * 20);
        }
        #pragma unroll
        for (int tl = 0; tl < 4; tl++) {
            lstm_step(&s[L1_OFF], &s[L1_OFF + 200], &A1[tl * 5], h1,  c1);
            lstm_step(&s[L2_OFF], &s[L2_OFF + 200], &B1[tl * 5], h2a, c2a);
            lstm_step(&s[L3_OFF], &s[L3_OFF + 200], h2a,         h2b, c2b);
        }
    }
    // last timestep (t=127) inputs live in A1[15..19], B1[15..19]

    // ---- FC head: concat [x1_last, x2_last, out1, out2] -> 20 ----
    float a0[20];
    #pragma unroll
    for (int j = 0; j < 5; j++) {
        a0[j]      = A1[15 + j];
        a0[5 + j]  = B1[15 + j];
        a0[10 + j] = h1[j];
        a0[15 + j] = h2b[j];
    }
    float a1[32];
    #pragma unroll
    for (int j = 0; j < 32; j++) {
        float acc = s[FB1 + j];
        #pragma unroll
        for (int k = 0; k < 20; k++) acc = fmaf(s[FW1 + j * 20 + k], a0[k], acc);
        a1[j] = fmaxf(acc, 0.0f);
    }
    float a2[32];
    #pragma unroll
    for (int j = 0; j < 32; j++) {
        float acc = s[FB2 + j];
        #pragma unroll
        for (int k = 0; k < 32; k++) acc = fmaf(s[FW2 + j * 32 + k], a1[k], acc);
        a2[j] = fmaxf(acc, 0.0f);
    }
    float a3[16];
    #pragma unroll
    for (int j = 0; j < 16; j++) {
        float acc = s[FB3 + j];
        #pragma unroll
        for (int k = 0; k < 32; k++) acc = fmaf(s[FW3 + j * 32 + k], a2[k], acc);
        a3[j] = fmaxf(acc, 0.0f);
    }
    float a4[16];
    #pragma unroll
    for (int j = 0; j < 16; j++) {
        float acc = s[FB4 + j];
        #pragma unroll
        for (int k = 0; k < 16; k++) acc = fmaf(s[FW4 + j * 16 + k], a3[k], acc);
        a4[j] = fmaxf(acc, 0.0f);
    }
    #pragma unroll
    for (int j = 0; j < 5; j++) {
        float acc = s[FB5 + j];
        #pragma unroll
        for (int k = 0; k < 16; k++) acc = fmaf(s[FW5 + j * 16 + k], a4[k], acc);
        p.out[(size_t)b * 5 + j] = acc;
    }
}

extern "C" void kernel_launch(void* const* d_in, const int* in_sizes, int n_in,
                              void* d_out, int out_size) {
    Params p;
    p.x1    = (const float*)d_in[0];
    p.x2    = (const float*)d_in[1];
    p.Wih1  = (const float*)d_in[2];
    p.Whh1  = (const float*)d_in[3];
    p.bih1  = (const float*)d_in[4];
    p.bhh1  = (const float*)d_in[5];
    p.Wih2a = (const float*)d_in[6];
    p.Whh2a = (const float*)d_in[7];
    p.bih2a = (const float*)d_in[8];
    p.bhh2a = (const float*)d_in[9];
    p.Wih2b = (const float*)d_in[10];
    p.Whh2b = (const float*)d_in[11];
    p.bih2b = (const float*)d_in[12];
    p.bhh2b = (const float*)d_in[13];
    p.W1 = (const float*)d_in[14];  p.b1 = (const float*)d_in[15];
    p.W2 = (const float*)d_in[16];  p.b2 = (const float*)d_in[17];
    p.W3 = (const float*)d_in[18];  p.b3 = (const float*)d_in[19];
    p.W4 = (const float*)d_in[20];  p.b4 = (const float*)d_in[21];
    p.W5 = (const float*)d_in[22];  p.b5 = (const float*)d_in[23];
    p.out = (float*)d_out;
    p.B   = in_sizes[0] / (TT * 5);

    int grid = (p.B + BLK - 1) / BLK;
    dynrnn_kernel<<<grid, BLK>>>(p);
}

// round 3
// speedup vs baseline: 6.2825x; 6.2825x over previous
#include <cuda_runtime.h>

#define TT   128
#define BLK  128
#define EPB  40          // elements per block: 4 warps x 10
#define RSTRIDE 220      // floats per role block in shared

// ---- shared layout (floats) ----
// per-LSTM role block: WihT[5][20] (100) + WhhT[5][20] (100) + Bsum[20] = 220
#define L1_OFF 0
#define FC_OFF 660
#define FW1 (FC_OFF)
#define FB1 (FW1+640)
#define FW2 (FB1+32)
#define FB2 (FW2+1024)
#define FW3 (FB2+32)
#define FB3 (FW3+512)
#define FW4 (FB3+16)
#define FB4 (FW4+256)
#define FW5 (FB4+16)
#define FB5 (FW5+80)
#define S_TOTAL (FB5+5)   // 3273 floats = ~13.1 KB

__device__ __forceinline__ float tanh_fast(float x) {
    float y;
    asm("tanh.approx.f32 %0, %1;" : "=f"(y) : "f"(x));
    return y;
}
__device__ __forceinline__ float sigm_fast(float x) {
    return fmaf(tanh_fast(0.5f * x), 0.5f, 0.5f);
}

// One H=5 LSTM cell step. sW: WihT[5][20] then WhhT[5][20] at +100.
// bias in registers. commit=false leaves state untouched (pipeline warm-up).
__device__ __forceinline__ void cell(const float* __restrict__ sW,
                                     const float* __restrict__ bias,
                                     const float* __restrict__ in,
                                     float* __restrict__ h,
                                     float* __restrict__ c,
                                     bool commit) {
    float g[20];
    #pragma unroll
    for (int m = 0; m < 20; m++) g[m] = bias[m];
    #pragma unroll
    for (int k = 0; k < 5; k++) {
        float xk = in[k];
        const float4* w4 = reinterpret_cast<const float4*>(sW + k * 20);
        #pragma unroll
        for (int q = 0; q < 5; q++) {
            float4 w = w4[q];
            g[4*q+0] = fmaf(w.x, xk, g[4*q+0]);
            g[4*q+1] = fmaf(w.y, xk, g[4*q+1]);
            g[4*q+2] = fmaf(w.z, xk, g[4*q+2]);
            g[4*q+3] = fmaf(w.w, xk, g[4*q+3]);
        }
    }
    #pragma unroll
    for (int k = 0; k < 5; k++) {
        float hk = h[k];
        const float4* u4 = reinterpret_cast<const float4*>(sW + 100 + k * 20);
        #pragma unroll
        for (int q = 0; q < 5; q++) {
            float4 u = u4[q];
            g[4*q+0] = fmaf(u.x, hk, g[4*q+0]);
            g[4*q+1] = fmaf(u.y, hk, g[4*q+1]);
            g[4*q+2] = fmaf(u.z, hk, g[4*q+2]);
            g[4*q+3] = fmaf(u.w, hk, g[4*q+3]);
        }
    }
    #pragma unroll
    for (int m = 0; m < 5; m++) {
        float ig = sigm_fast(g[m]);
        float fg = sigm_fast(g[5 + m]);
        float gg = tanh_fast(g[10 + m]);
        float og = sigm_fast(g[15 + m]);
        float cm = fmaf(fg, c[m], ig * gg);
        float hm = og * tanh_fast(cm);
        c[m] = commit ? cm : c[m];
        h[m] = commit ? hm : h[m];
    }
}

// Load one 4-timestep chunk (20 floats, 16B-aligned).
__device__ __forceinline__ void load_chunk(float* dst, const float* src) {
    const float4* s4 = reinterpret_cast<const float4*>(src);
    #pragma unroll
    for (int i = 0; i < 5; i++) {
        float4 v = __ldg(s4 + i);
        dst[4*i+0] = v.x; dst[4*i+1] = v.y;
        dst[4*i+2] = v.z; dst[4*i+3] = v.w;
    }
}

struct Params {
    const float *x1, *x2;
    const float *Wih1, *Whh1, *bih1, *bhh1;
    const float *Wih2a, *Whh2a, *bih2a, *bhh2a;
    const float *Wih2b, *Whh2b, *bih2b, *bhh2b;
    const float *W1, *b1, *W2, *b2, *W3, *b3, *W4, *b4, *W5, *b5;
    float* out;
    int B;
};

__global__ __launch_bounds__(BLK)
void dynrnn_kernel(Params p) {
    __shared__ float s[S_TOTAL];
    const int tid = threadIdx.x;

    // ---- cooperative weight staging (transposed LSTM weights, role blocks) ----
    {
        const float* srcs[6] = { p.Wih1, p.Whh1, p.Wih2a, p.Whh2a, p.Wih2b, p.Whh2b };
        const int    offs[6] = { 0, 100, RSTRIDE, RSTRIDE+100, 2*RSTRIDE, 2*RSTRIDE+100 };
        for (int m = 0; m < 6; m++) {
            const float* W = srcs[m];
            int off = offs[m];
            for (int i = tid; i < 100; i += BLK) {
                int j = i / 5, k = i % 5;
                s[off + k * 20 + j] = W[i];
            }
        }
        for (int i = tid; i < 20; i += BLK) {
            s[0*RSTRIDE + 200 + i] = p.bih1[i]  + p.bhh1[i];
            s[1*RSTRIDE + 200 + i] = p.bih2a[i] + p.bhh2a[i];
            s[2*RSTRIDE + 200 + i] = p.bih2b[i] + p.bhh2b[i];
        }
        for (int i = tid; i < 640;  i += BLK) s[FW1 + i] = p.W1[i];
        for (int i = tid; i < 32;   i += BLK) s[FB1 + i] = p.b1[i];
        for (int i = tid; i < 1024; i += BLK) s[FW2 + i] = p.W2[i];
        for (int i = tid; i < 32;   i += BLK) s[FB2 + i] = p.b2[i];
        for (int i = tid; i < 512;  i += BLK) s[FW3 + i] = p.W3[i];
        for (int i = tid; i < 16;   i += BLK) s[FB3 + i] = p.b3[i];
        for (int i = tid; i < 256;  i += BLK) s[FW4 + i] = p.W4[i];
        for (int i = tid; i < 16;   i += BLK) s[FB4 + i] = p.b4[i];
        for (int i = tid; i < 80;   i += BLK) s[FW5 + i] = p.W5[i];
        for (int i = tid; i < 5;    i += BLK) s[FB5 + i] = p.b5[i];
    }
    __syncthreads();

    // ---- lane/role mapping: 3 lanes per element, 10 elements per warp ----
    const int w   = tid >> 5;
    const int l   = tid & 31;
    const int grp = l / 3;           // 0..9 (10 = invalid for l in {30,31})
    const int r   = l - 3 * grp;     // role 0: lstm1, 1: lstm2a, 2: lstm2b
    const bool lane_ok = (l < 30);

    const int e = blockIdx.x * EPB + w * 10 + grp;
    const bool valid = lane_ok && (e < p.B);
    int ec = e < p.B ? e : (p.B - 1);          // clamp for safe loads

    const float* xp = ((r == 1) ? p.x2 : p.x1) + (size_t)ec * (TT * 5);
    const float* sW = s + r * RSTRIDE;
    const bool isr2 = (r == 2);

    // hoist fused bias into registers (one cell per lane)
    float bias[20];
    {
        const float4* b4 = reinterpret_cast<const float4*>(sW + 200);
        #pragma unroll
        for (int q = 0; q < 5; q++) {
            float4 v = b4[q];
            bias[4*q+0] = v.x; bias[4*q+1] = v.y;
            bias[4*q+2] = v.z; bias[4*q+3] = v.w;
        }
    }

    float h[5], c[5], nh[5];
    #pragma unroll
    for (int m = 0; m < 5; m++) { h[m] = 0.0f; c[m] = 0.0f; nh[m] = 0.0f; }

    float A[20], Bb[20];
    load_chunk(A, xp);

    #pragma unroll 1
    for (int it = 0; it < 16; it++) {
        load_chunk(Bb, xp + (2 * it + 1) * 20);
        #pragma unroll
        for (int tl = 0; tl < 4; tl++) {
            float in[5];
            #pragma unroll
            for (int j = 0; j < 5; j++) in[j] = isr2 ? nh[j] : A[tl * 5 + j];
            // role-2 lane skips commit on the very first global step (pipeline warm-up)
            bool commit = !(isr2 && (it == 0) && (tl == 0));
            cell(sW, bias, in, h, c, commit);
            #pragma unroll
            for (int j = 0; j < 5; j++) nh[j] = __shfl_up_sync(0xFFFFFFFFu, h[j], 1);
        }
        int ci = 2 * it + 2; if (ci > 31) ci = 31;
        load_chunk(A, xp + ci * 20);
        #pragma unroll
        for (int tl = 0; tl < 4; tl++) {
            float in[5];
            #pragma unroll
            for (int j = 0; j < 5; j++) in[j] = isr2 ? nh[j] : Bb[tl * 5 + j];
            cell(sW, bias, in, h, c, true);
            #pragma unroll
            for (int j = 0; j < 5; j++) nh[j] = __shfl_up_sync(0xFFFFFFFFu, h[j], 1);
        }
    }

    // role-2 drains the pipeline: final step consumes h2a(127)
    if (isr2) {
        cell(sW, bias, nh, h, c, true);
    }

    // ---- gather results onto role-0 lanes ----
    // last timestep inputs live in Bb[15..19] (chunk 31 = steps 124..127)
    float x2l[5], o2[5];
    #pragma unroll
    for (int j = 0; j < 5; j++) {
        x2l[j] = __shfl_down_sync(0xFFFFFFFFu, Bb[15 + j], 1);  // from role 1
        o2[j]  = __shfl_down_sync(0xFFFFFFFFu, h[j], 2);        // from role 2
    }

    if (valid && r == 0) {
        float a0[20];
        #pragma unroll
        for (int j = 0; j < 5; j++) {
            a0[j]      = Bb[15 + j];  // x1 last
            a0[5 + j]  = x2l[j];      // x2 last
            a0[10 + j] = h[j];        // out1
            a0[15 + j] = o2[j];       // out2
        }
        float a1[32];
        #pragma unroll
        for (int j = 0; j < 32; j++) {
            float acc = s[FB1 + j];
            #pragma unroll
            for (int k = 0; k < 20; k++) acc = fmaf(s[FW1 + j * 20 + k], a0[k], acc);
            a1[j] = fmaxf(acc, 0.0f);
        }
        float a2[32];
        #pragma unroll
        for (int j = 0; j < 32; j++) {
            float acc = s[FB2 + j];
            #pragma unroll
            for (int k = 0; k < 32; k++) acc = fmaf(s[FW2 + j * 32 + k], a1[k], acc);
            a2[j] = fmaxf(acc, 0.0f);
        }
        float a3[16];
        #pragma unroll
        for (int j = 0; j < 16; j++) {
            float acc = s[FB3 + j];
            #pragma unroll
            for (int k = 0; k < 32; k++) acc = fmaf(s[FW3 + j * 32 + k], a2[k], acc);
            a3[j] = fmaxf(acc, 0.0f);
        }
        float a4[16];
        #pragma unroll
        for (int j = 0; j < 16; j++) {
            float acc = s[FB4 + j];
            #pragma unroll
            for (int k = 0; k < 16; k++) acc = fmaf(s[FW4 + j * 16 + k], a3[k], acc);
            a4[j] = fmaxf(acc, 0.0f);
        }
        #pragma unroll
        for (int j = 0; j < 5; j++) {
            float acc = s[FB5 + j];
            #pragma unroll
            for (int k = 0; k < 16; k++) acc = fmaf(s[FW5 + j * 16 + k], a4[k], acc);
            p.out[(size_t)e * 5 + j] = acc;
        }
    }
}

extern "C" void kernel_launch(void* const* d_in, const int* in_sizes, int n_in,
                              void* d_out, int out_size) {
    Params p;
    p.x1    = (const float*)d_in[0];
    p.x2    = (const float*)d_in[1];
    p.Wih1  = (const float*)d_in[2];
    p.Whh1  = (const float*)d_in[3];
    p.bih1  = (const float*)d_in[4];
    p.bhh1  = (const float*)d_in[5];
    p.Wih2a = (const float*)d_in[6];
    p.Whh2a = (const float*)d_in[7];
    p.bih2a = (const float*)d_in[8];
    p.bhh2a = (const float*)d_in[9];
    p.Wih2b = (const float*)d_in[10];
    p.Whh2b = (const float*)d_in[11];
    p.bih2b = (const float*)d_in[12];
    p.bhh2b = (const float*)d_in[13];
    p.W1 = (const float*)d_in[14];  p.b1 = (const float*)d_in[15];
    p.W2 = (const float*)d_in[16];  p.b2 = (const float*)d_in[17];
    p.W3 = (const float*)d_in[18];  p.b3 = (const float*)d_in[19];
    p.W4 = (const float*)d_in[20];  p.b4 = (const float*)d_in[21];
    p.W5 = (const float*)d_in[22];  p.b5 = (const float*)d_in[23];
    p.out = (float*)d_out;
    p.B   = in_sizes[0] / (TT * 5);

    int grid = (p.B + EPB - 1) / EPB;   // 410 blocks for B=16384
    dynrnn_kernel<<<grid, BLK>>>(p);
}